// round 6
// baseline (speedup 1.0000x reference)
#include <cuda_runtime.h>
#include <cuda_bf16.h>
#include <cstdint>

// Problem dims
#define NUM_NODES 1000000
#define HIDDEN    128
#define OUT_DIM   64
#define FANOUT    16
#define N_SRC0    1048576
#define N_DST0    65536
#define N_DST1    4096

#define TILE0     64                      // rows per tile unit
#define NUNITS    (N_DST0 / TILE0)        // 1024
#define N_GATHER  444                     // producer CTAs
#define N_GEMM    148                     // consumer CTAs
#define GRID0     (N_GATHER + N_GEMM)     // 592 = 4/SM on 148 SMs

// ---------------- scratch (static device globals; no allocations) ----------
__device__ uint32_t g_X0[(size_t)N_DST0 * 256];   // tf32 BITS [self|mean]
__device__ float    g_H1[(size_t)N_DST0 * 128];   // layer-0 output (post-ReLU)
__device__ float    g_X1[(size_t)N_DST1 * 256];   // [self | mean] per dst1 row
__device__ uint32_t g_W0T[256 * 128];             // tf32 BITS: [k][n] = cat(Ws0,Wn0)^T
__device__ float    g_b0[128];                    // b_self0 + b_neigh0
__device__ float    g_WfT[256 * 64];              // [k][n] = (W_out @ cat(Ws1,Wn1))^T
__device__ float    g_bf[64];                     // W_out @ (bs1+bn1) + b_out
__device__ int      g_flag[NUNITS];               // tile-ready flags

// ---------------- helpers --------------------------------------------------
__device__ __forceinline__ uint32_t f2tf32(float f) {
    uint32_t r; asm("cvt.rna.tf32.f32 %0, %1;" : "=r"(r) : "f"(f)); return r;
}

__device__ __forceinline__ void mma_tf32(float c[4],
                                         uint32_t a0, uint32_t a1, uint32_t a2, uint32_t a3,
                                         uint32_t b0, uint32_t b1) {
    asm volatile(
        "mma.sync.aligned.m16n8k8.row.col.f32.tf32.tf32.f32 "
        "{%0,%1,%2,%3}, {%4,%5,%6,%7}, {%8,%9}, {%0,%1,%2,%3};"
        : "+f"(c[0]), "+f"(c[1]), "+f"(c[2]), "+f"(c[3])
        : "r"(a0), "r"(a1), "r"(a2), "r"(a3), "r"(b0), "r"(b1));
}

// ---------------- prep: pack layer-0 weights (tf32 bits) + zero flags ------
__global__ void prep_w0(const float* __restrict__ Ws0, const float* __restrict__ bs0,
                        const float* __restrict__ Wn0, const float* __restrict__ bn0) {
    int idx = blockIdx.x * blockDim.x + threadIdx.x;   // 32768 total
    if (idx < 256 * 128) {
        int k = idx >> 7;
        int n = idx & 127;
        float v = (k < 128) ? Ws0[n * 128 + k] : Wn0[n * 128 + (k - 128)];
        g_W0T[idx] = f2tf32(v);
    }
    if (idx < 128) g_b0[idx] = bs0[idx] + bn0[idx];
    if (idx < NUNITS) g_flag[idx] = 0;
}

// ---------------- prep: fuse layer-1 + output projection -------------------
__global__ void prep_wf(const float* __restrict__ Ws1, const float* __restrict__ bs1,
                        const float* __restrict__ Wn1, const float* __restrict__ bn1,
                        const float* __restrict__ Wout, const float* __restrict__ bout) {
    int idx = blockIdx.x * blockDim.x + threadIdx.x;   // 16384 total
    if (idx < 256 * 64) {
        int k = idx >> 6;
        int n = idx & 63;
        float acc = 0.f;
        if (k < 128) {
            #pragma unroll 4
            for (int r = 0; r < 128; r++) acc += Wout[n * 128 + r] * Ws1[r * 128 + k];
        } else {
            int kk = k - 128;
            #pragma unroll 4
            for (int r = 0; r < 128; r++) acc += Wout[n * 128 + r] * Wn1[r * 128 + kk];
        }
        g_WfT[k * 64 + n] = acc;
    }
    if (idx < 64) {
        float acc = bout[idx];
        #pragma unroll 4
        for (int r = 0; r < 128; r++) acc += Wout[idx * 128 + r] * (bs1[r] + bn1[r]);
        g_bf[idx] = acc;
    }
}

// ---------------- layer-0: CTA-role-split producer/consumer ----------------
// Producers (bid < N_GATHER): R2-style warp-per-row gather+mean, tf32-convert,
// write X0 tile, set flag. Consumers: spin on flag, tf32 MMA 64x128x256 with
// X0 read from L2, fused bias+ReLU -> g_H1.
__global__ __launch_bounds__(256, 4) void layer0_pc_kernel(
    const float* __restrict__ emb, const int* __restrict__ input_nodes,
    const int* __restrict__ nbr0) {
    __shared__ uint32_t As[TILE0][36];     // 9216 B
    __shared__ uint32_t Bs[32][132];       // 16896 B

    const int tid  = threadIdx.x;
    const int lane = tid & 31;
    const int wid  = tid >> 5;

    if (blockIdx.x < N_GATHER) {
        // ===================== PRODUCER =====================
        const float4* E = (const float4*)emb;               // row = 32 float4
        const float inv = 1.0f / (float)FANOUT;
        uint4* X = (uint4*)g_X0;                             // row = 64 uint4? no: 256 words = 64 uint4

        for (int t = blockIdx.x; t < NUNITS; t += N_GATHER) {
            const int base = t * TILE0;
            #pragma unroll 2
            for (int rr = 0; rr < 8; rr++) {
                const int r = base + wid * 8 + rr;
                int nj = (lane < FANOUT)
                    ? input_nodes[nbr0[(size_t)r * FANOUT + lane]] : 0;
                int self = input_nodes[r];

                float4 s = E[(size_t)self * 32 + lane];
                float ax = 0.f, ay = 0.f, az = 0.f, aw = 0.f;
                #pragma unroll
                for (int q = 0; q < FANOUT; q++) {
                    int g = __shfl_sync(0xffffffffu, nj, q);
                    float4 v = E[(size_t)g * 32 + lane];
                    ax += v.x; ay += v.y; az += v.z; aw += v.w;
                }
                uint4 ts; ts.x = f2tf32(s.x); ts.y = f2tf32(s.y);
                ts.z = f2tf32(s.z); ts.w = f2tf32(s.w);
                X[(size_t)r * 64 + lane] = ts;
                uint4 tn; tn.x = f2tf32(ax * inv); tn.y = f2tf32(ay * inv);
                tn.z = f2tf32(az * inv); tn.w = f2tf32(aw * inv);
                X[(size_t)r * 64 + 32 + lane] = tn;
            }
            __syncthreads();
            __threadfence();
            if (tid == 0) *((volatile int*)&g_flag[t]) = 1;
        }
    } else {
        // ===================== CONSUMER =====================
        const int cb = blockIdx.x - N_GATHER;     // 0..147
        const int lm = lane >> 2;                 // 0..7
        const int lk = lane & 3;                  // 0..3
        const int wm = wid >> 2;                  // 0..1 -> rows wm*32..
        const int wn = wid & 3;                   // 0..3 -> cols wn*32..

        for (int t = cb; t < NUNITS; t += N_GEMM) {
            if (tid == 0) {
                while (*((volatile int*)&g_flag[t]) == 0) __nanosleep(64);
            }
            __syncthreads();

            const uint32_t* __restrict__ Ab = g_X0 + (size_t)t * TILE0 * 256;

            float acc[2][4][4];
            #pragma unroll
            for (int a = 0; a < 2; a++)
                #pragma unroll
                for (int b = 0; b < 4; b++)
                    #pragma unroll
                    for (int c = 0; c < 4; c++) acc[a][b][c] = 0.f;

            for (int k0 = 0; k0 < 256; k0 += 32) {
                // stage A chunk: 64 rows x 32 k = 512 uint4 (L2-hot)
                #pragma unroll
                for (int it = 0; it < 2; it++) {
                    int idx = it * 256 + tid;
                    int row = idx >> 3;
                    int c4  = idx & 7;
                    *(uint4*)&As[row][c4 * 4] =
                        *(const uint4*)(Ab + (size_t)row * 256 + k0 + c4 * 4);
                }
                // stage B chunk: 32 k x 128 n = 1024 uint4/4? -> 1024 words*4 = 1024 uint4
                #pragma unroll
                for (int it = 0; it < 4; it++) {
                    int idx = it * 256 + tid;
                    int kk = idx >> 5;
                    int n4 = idx & 31;
                    *(uint4*)&Bs[kk][n4 * 4] =
                        *(const uint4*)&g_W0T[(size_t)(k0 + kk) * 128 + n4 * 4];
                }
                __syncthreads();

                #pragma unroll
                for (int kk = 0; kk < 4; kk++) {
                    const int k8 = kk * 8;
                    uint32_t af[2][4], bf[4][2];
                    #pragma unroll
                    for (int mt = 0; mt < 2; mt++) {
                        int mrow = wm * 32 + mt * 16 + lm;
                        af[mt][0] = As[mrow    ][k8 + lk];
                        af[mt][1] = As[mrow + 8][k8 + lk];
                        af[mt][2] = As[mrow    ][k8 + lk + 4];
                        af[mt][3] = As[mrow + 8][k8 + lk + 4];
                    }
                    #pragma unroll
                    for (int nt = 0; nt < 4; nt++) {
                        int ncol = wn * 32 + nt * 8 + lm;
                        bf[nt][0] = Bs[k8 + lk    ][ncol];
                        bf[nt][1] = Bs[k8 + lk + 4][ncol];
                    }
                    #pragma unroll
                    for (int mt = 0; mt < 2; mt++)
                        #pragma unroll
                        for (int nt = 0; nt < 4; nt++)
                            mma_tf32(acc[mt][nt], af[mt][0], af[mt][1], af[mt][2], af[mt][3],
                                     bf[nt][0], bf[nt][1]);
                }
                __syncthreads();
            }

            // epilogue: bias + relu -> g_H1
            float2* __restrict__ H2 = (float2*)g_H1;    // row stride = 64 float2
            #pragma unroll
            for (int nt = 0; nt < 4; nt++) {
                int col = wn * 32 + nt * 8 + lk * 2;
                float bv0 = g_b0[col], bv1 = g_b0[col + 1];
                #pragma unroll
                for (int mt = 0; mt < 2; mt++) {
                    size_t row0 = (size_t)t * TILE0 + wm * 32 + mt * 16 + lm;
                    float2 v0 = make_float2(fmaxf(acc[mt][nt][0] + bv0, 0.f),
                                            fmaxf(acc[mt][nt][1] + bv1, 0.f));
                    float2 v1 = make_float2(fmaxf(acc[mt][nt][2] + bv0, 0.f),
                                            fmaxf(acc[mt][nt][3] + bv1, 0.f));
                    H2[row0 * 64 + (col >> 1)]       = v0;
                    H2[(row0 + 8) * 64 + (col >> 1)] = v1;
                }
            }
        }
    }
}

// ---------------- layer-1 gather: build X1 [N_DST1, 256] from g_H1 ---------
__global__ __launch_bounds__(256) void gather1_kernel(const int* __restrict__ nbr1) {
    int warp = (blockIdx.x * blockDim.x + threadIdx.x) >> 5;
    int lane = threadIdx.x & 31;
    if (warp >= N_DST1) return;

    int nj = 0;
    if (lane < FANOUT) nj = nbr1[warp * FANOUT + lane];

    const float4* H = (const float4*)g_H1;                // row stride = 32 float4
    float4 s = H[(size_t)warp * 32 + lane];
    float ax = 0.f, ay = 0.f, az = 0.f, aw = 0.f;
    #pragma unroll
    for (int j = 0; j < FANOUT; j++) {
        int g = __shfl_sync(0xffffffffu, nj, j);
        float4 v = H[(size_t)g * 32 + lane];
        ax += v.x; ay += v.y; az += v.z; aw += v.w;
    }
    const float inv = 1.0f / (float)FANOUT;
    float4* X = (float4*)g_X1;
    X[(size_t)warp * 64 + lane]      = s;
    X[(size_t)warp * 64 + 32 + lane] = make_float4(ax * inv, ay * inv, az * inv, aw * inv);
}

// ---------------- gemm1: out = g_X1 @ g_WfT + g_bf -------------------------
__global__ __launch_bounds__(256) void gemm1_kernel(float* __restrict__ C) {
    __shared__ float Bs[64][65];
    int tid = threadIdx.x;
    int r = blockIdx.x * 4 + (tid >> 6);
    int n = tid & 63;
    float acc = g_bf[n];
    for (int k0 = 0; k0 < 256; k0 += 64) {
        for (int i = tid; i < 64 * 64; i += 256)
            Bs[i >> 6][i & 63] = g_WfT[(size_t)(k0 + (i >> 6)) * 64 + (i & 63)];
        __syncthreads();
        const float* Ar = g_X1 + (size_t)r * 256 + k0;
        #pragma unroll 16
        for (int k = 0; k < 64; k++) acc = fmaf(Ar[k], Bs[k][n], acc);
        __syncthreads();
    }
    C[(size_t)r * 64 + n] = acc;
}

// ---------------- launch ---------------------------------------------------
extern "C" void kernel_launch(void* const* d_in, const int* in_sizes, int n_in,
                              void* d_out, int out_size) {
    const float* emb      = (const float*)d_in[0];
    const float* Ws0      = (const float*)d_in[1];
    const float* bs0      = (const float*)d_in[2];
    const float* Wn0      = (const float*)d_in[3];
    const float* bn0      = (const float*)d_in[4];
    const float* Ws1      = (const float*)d_in[5];
    const float* bs1      = (const float*)d_in[6];
    const float* Wn1      = (const float*)d_in[7];
    const float* bn1      = (const float*)d_in[8];
    const float* Wout     = (const float*)d_in[9];
    const float* bout     = (const float*)d_in[10];
    const int*   in_nodes = (const int*)d_in[11];
    const int*   nbr0     = (const int*)d_in[12];
    const int*   nbr1     = (const int*)d_in[13];
    float* out = (float*)d_out;

    // weight prep + flag reset (tiny; ordered before layer0 on the stream)
    prep_w0<<<128, 256>>>(Ws0, bs0, Wn0, bn0);
    prep_wf<<<64, 256>>>(Ws1, bs1, Wn1, bn1, Wout, bout);

    // layer 0: cross-CTA producer/consumer (gather overlapped with MMA)
    layer0_pc_kernel<<<GRID0, 256>>>(emb, in_nodes, nbr0);

    // layer 1 gather, then fused (layer1 + output-projection) GEMM
    gather1_kernel<<<(N_DST1 * 32) / 256, 256>>>(nbr1);
    gemm1_kernel<<<N_DST1 / 4, 256>>>(out);
}

// round 7
// speedup vs baseline: 1.1825x; 1.1825x over previous
#include <cuda_runtime.h>
#include <cuda_bf16.h>
#include <cstdint>

// Problem dims
#define NUM_NODES 1000000
#define HIDDEN    128
#define OUT_DIM   64
#define FANOUT    16
#define N_SRC0    1048576
#define N_DST0    65536
#define N_DST1    4096

// ---------------- scratch (static device globals; no allocations) ----------
__device__ uint32_t g_X0[(size_t)N_DST0 * 256];   // tf32 BITS [self|mean]
__device__ float    g_H1[(size_t)N_DST0 * 128];   // layer-0 output (post-ReLU)
__device__ float    g_X1[(size_t)N_DST1 * 256];   // [self | mean] per dst1 row
__device__ uint32_t g_W0T[256 * 128];             // tf32 BITS: [k][n] = cat(Ws0,Wn0)^T
__device__ float    g_b0[128];                    // b_self0 + b_neigh0
__device__ float    g_WfT[256 * 64];              // [k][n] = (W_out @ cat(Ws1,Wn1))^T
__device__ float    g_bf[64];                     // W_out @ (bs1+bn1) + b_out

// ---------------- helpers --------------------------------------------------
__device__ __forceinline__ uint32_t f2tf32(float f) {
    uint32_t r; asm("cvt.rna.tf32.f32 %0, %1;" : "=r"(r) : "f"(f)); return r;
}

__device__ __forceinline__ unsigned long long addx2(unsigned long long a,
                                                    unsigned long long b) {
    unsigned long long r;
    asm("add.rn.f32x2 %0, %1, %2;" : "=l"(r) : "l"(a), "l"(b));
    return r;
}

__device__ __forceinline__ void unpack2(unsigned long long v, float& a, float& b) {
    asm("mov.b64 {%0, %1}, %2;" : "=f"(a), "=f"(b) : "l"(v));
}

__device__ __forceinline__ uint32_t smem_u32(const void* p) {
    uint32_t a;
    asm("{ .reg .u64 t; cvta.to.shared.u64 t, %1; cvt.u32.u64 %0, t; }" : "=r"(a) : "l"(p));
    return a;
}

__device__ __forceinline__ void mma_tf32(float c[4],
                                         uint32_t a0, uint32_t a1, uint32_t a2, uint32_t a3,
                                         uint32_t b0, uint32_t b1) {
    asm volatile(
        "mma.sync.aligned.m16n8k8.row.col.f32.tf32.tf32.f32 "
        "{%0,%1,%2,%3}, {%4,%5,%6,%7}, {%8,%9}, {%0,%1,%2,%3};"
        : "+f"(c[0]), "+f"(c[1]), "+f"(c[2]), "+f"(c[3])
        : "r"(a0), "r"(a1), "r"(a2), "r"(a3), "r"(b0), "r"(b1));
}

// ---------------- prep: pack layer-0 weights (tf32 bits) -------------------
__global__ void prep_w0(const float* __restrict__ Ws0, const float* __restrict__ bs0,
                        const float* __restrict__ Wn0, const float* __restrict__ bn0) {
    int idx = blockIdx.x * blockDim.x + threadIdx.x;   // 32768 total
    if (idx < 256 * 128) {
        int k = idx >> 7;
        int n = idx & 127;
        float v = (k < 128) ? Ws0[n * 128 + k] : Wn0[n * 128 + (k - 128)];
        g_W0T[idx] = f2tf32(v);
    }
    if (idx < 128) g_b0[idx] = bs0[idx] + bn0[idx];
}

// ---------------- prep: fuse layer-1 + output projection -------------------
__global__ void prep_wf(const float* __restrict__ Ws1, const float* __restrict__ bs1,
                        const float* __restrict__ Wn1, const float* __restrict__ bn1,
                        const float* __restrict__ Wout, const float* __restrict__ bout) {
    int idx = blockIdx.x * blockDim.x + threadIdx.x;   // 16384 total
    if (idx < 256 * 64) {
        int k = idx >> 6;
        int n = idx & 63;
        float acc = 0.f;
        if (k < 128) {
            #pragma unroll 4
            for (int r = 0; r < 128; r++) acc += Wout[n * 128 + r] * Ws1[r * 128 + k];
        } else {
            int kk = k - 128;
            #pragma unroll 4
            for (int r = 0; r < 128; r++) acc += Wout[n * 128 + r] * Wn1[r * 128 + kk];
        }
        g_WfT[k * 64 + n] = acc;
    }
    if (idx < 64) {
        float acc = bout[idx];
        #pragma unroll 4
        for (int r = 0; r < 128; r++) acc += Wout[idx * 128 + r] * (bs1[r] + bn1[r]);
        g_bf[idx] = acc;
    }
}

// ---------------- layer-0 gather via cp.async deep pipeline ----------------
// Each 128-thread CTA handles 64 dst rows (16 per warp). Per warp: double-
// buffered staging of 17 source rows (self + 16 nbrs, 512B each) filled by
// cp.async.cg; reduce from smem with packed f32x2 adds; write tf32 X0.
#define GCHUNK   64
#define RPW      16                      // rows per warp
#define STG_ROW  512                     // bytes per staged source row
#define STG_BUF  (17 * STG_ROW)          // 8704 per buffer
#define STG_WARP (2 * STG_BUF)           // 17408 per warp
#define GSM_STAGE (4 * STG_WARP)         // 69632
#define GSM_BYTES (GSM_STAGE + GCHUNK * FANOUT * 4 + GCHUNK * 4)   // 73984

__global__ __launch_bounds__(128, 3) void gather0_cp_kernel(
    const float* __restrict__ emb, const int* __restrict__ input_nodes,
    const int* __restrict__ nbr0) {
    extern __shared__ uint8_t gsm[];
    int* s_idx  = (int*)(gsm + GSM_STAGE);            // [64*16]
    int* s_self = s_idx + GCHUNK * FANOUT;            // [64]

    const int tid  = threadIdx.x;
    const int lane = tid & 31;
    const int wid  = tid >> 5;
    const int base = blockIdx.x * GCHUNK;

    // stage composed indices (coalesced two-level loads)
    #pragma unroll
    for (int it = 0; it < (GCHUNK * FANOUT) / 128; it++) {    // 8 iters
        int i = it * 128 + tid;
        s_idx[i] = input_nodes[nbr0[(size_t)base * FANOUT + i]];
    }
    if (tid < GCHUNK) s_self[tid] = input_nodes[base + tid];
    __syncthreads();

    uint8_t* wstage = gsm + wid * STG_WARP;
    const int rbase = wid * RPW;

    auto issue_row = [&](int rl, int buf) {
        uint8_t* dbase = wstage + buf * STG_BUF + lane * 16;
        const int row = rbase + rl;
        {
            int g = s_self[row];
            uint32_t d = smem_u32(dbase);
            const float* s = emb + (size_t)g * HIDDEN + lane * 4;
            asm volatile("cp.async.cg.shared.global [%0], [%1], 16;" :: "r"(d), "l"(s));
        }
        #pragma unroll
        for (int j = 0; j < FANOUT; j++) {
            int g = s_idx[row * FANOUT + j];
            uint32_t d = smem_u32(dbase + (j + 1) * STG_ROW);
            const float* s = emb + (size_t)g * HIDDEN + lane * 4;
            asm volatile("cp.async.cg.shared.global [%0], [%1], 16;" :: "r"(d), "l"(s));
        }
        asm volatile("cp.async.commit_group;" ::: "memory");
    };

    auto reduce_store = [&](int rl, int buf) {
        const uint8_t* sbase = wstage + buf * STG_BUF + lane * 16;
        ulonglong2 self = *(const ulonglong2*)(sbase);
        ulonglong2 acc  = *(const ulonglong2*)(sbase + STG_ROW);
        #pragma unroll
        for (int j = 2; j <= FANOUT; j++) {
            ulonglong2 v = *(const ulonglong2*)(sbase + j * STG_ROW);
            acc.x = addx2(acc.x, v.x);
            acc.y = addx2(acc.y, v.y);
        }
        float s0, s1, s2, s3, m0, m1, m2, m3;
        unpack2(self.x, s0, s1); unpack2(self.y, s2, s3);
        unpack2(acc.x,  m0, m1); unpack2(acc.y,  m2, m3);
        const float inv = 1.0f / (float)FANOUT;
        uint4 ts, tn;
        ts.x = f2tf32(s0); ts.y = f2tf32(s1); ts.z = f2tf32(s2); ts.w = f2tf32(s3);
        tn.x = f2tf32(m0 * inv); tn.y = f2tf32(m1 * inv);
        tn.z = f2tf32(m2 * inv); tn.w = f2tf32(m3 * inv);
        size_t row = (size_t)base + rbase + rl;
        *(uint4*)&g_X0[row * 256 + lane * 4]       = ts;
        *(uint4*)&g_X0[row * 256 + 128 + lane * 4] = tn;
    };

    issue_row(0, 0);
    issue_row(1, 1);
    #pragma unroll
    for (int i = 0; i < RPW; i++) {
        if (i == RPW - 1) {
            asm volatile("cp.async.wait_group 0;" ::: "memory");
        } else {
            asm volatile("cp.async.wait_group 1;" ::: "memory");
        }
        reduce_store(i, i & 1);
        if (i + 2 < RPW) issue_row(i + 2, i & 1);
    }
}

// ---------------- gemm0 (tensor cores, tf32) -------------------------------
// g_H1 = relu(X0 @ W0T + b0).  M=65536, N=128, K=256. 128x128 CTA tile,
// BK=32, 8 warps 2(m) x 4(n). A and B already tf32 bits -> raw staging.
__global__ __launch_bounds__(256) void gemm0_tc_kernel() {
    __shared__ uint32_t As[128][36];
    __shared__ uint32_t Bs[32][132];

    const int tid  = threadIdx.x;
    const int l    = tid & 31;
    const int lm   = l >> 2;
    const int lk   = l & 3;
    const int wid  = tid >> 5;
    const int wm   = wid >> 2;
    const int wn   = wid & 3;
    const size_t block_row = (size_t)blockIdx.x * 128;
    const uint32_t* __restrict__ A = g_X0 + block_row * 256;
    const uint32_t* __restrict__ B = g_W0T;

    float acc[4][4][4];
    #pragma unroll
    for (int i = 0; i < 4; i++)
        #pragma unroll
        for (int j = 0; j < 4; j++)
            #pragma unroll
            for (int c = 0; c < 4; c++) acc[i][j][c] = 0.f;

    for (int k0 = 0; k0 < 256; k0 += 32) {
        #pragma unroll
        for (int it = 0; it < 4; it++) {
            int idx = it * 256 + tid;
            int row = idx >> 3;
            int c4  = idx & 7;
            *(uint4*)&As[row][c4 * 4] =
                *(const uint4*)(A + (size_t)row * 256 + k0 + c4 * 4);
        }
        #pragma unroll
        for (int it = 0; it < 4; it++) {
            int idx = it * 256 + tid;
            int kk = idx >> 5;
            int n4 = idx & 31;
            *(uint4*)&Bs[kk][n4 * 4] =
                *(const uint4*)(B + (size_t)(k0 + kk) * 128 + n4 * 4);
        }
        __syncthreads();

        #pragma unroll
        for (int kk = 0; kk < 4; kk++) {
            const int k8 = kk * 8;
            uint32_t af[4][4], bf[4][2];
            #pragma unroll
            for (int mt = 0; mt < 4; mt++) {
                int mrow = wm * 64 + mt * 16 + lm;
                af[mt][0] = As[mrow    ][k8 + lk];
                af[mt][1] = As[mrow + 8][k8 + lk];
                af[mt][2] = As[mrow    ][k8 + lk + 4];
                af[mt][3] = As[mrow + 8][k8 + lk + 4];
            }
            #pragma unroll
            for (int nt = 0; nt < 4; nt++) {
                int ncol = wn * 32 + nt * 8 + lm;
                bf[nt][0] = Bs[k8 + lk    ][ncol];
                bf[nt][1] = Bs[k8 + lk + 4][ncol];
            }
            #pragma unroll
            for (int mt = 0; mt < 4; mt++)
                #pragma unroll
                for (int nt = 0; nt < 4; nt++)
                    mma_tf32(acc[mt][nt], af[mt][0], af[mt][1], af[mt][2], af[mt][3],
                             bf[nt][0], bf[nt][1]);
        }
        __syncthreads();
    }

    float2* __restrict__ H2 = (float2*)g_H1;      // row stride = 64 float2
    #pragma unroll
    for (int nt = 0; nt < 4; nt++) {
        int col = wn * 32 + nt * 8 + lk * 2;
        float bv0 = g_b0[col], bv1 = g_b0[col + 1];
        #pragma unroll
        for (int mt = 0; mt < 4; mt++) {
            size_t row0 = block_row + wm * 64 + mt * 16 + lm;
            float2 v0 = make_float2(fmaxf(acc[mt][nt][0] + bv0, 0.f),
                                    fmaxf(acc[mt][nt][1] + bv1, 0.f));
            float2 v1 = make_float2(fmaxf(acc[mt][nt][2] + bv0, 0.f),
                                    fmaxf(acc[mt][nt][3] + bv1, 0.f));
            H2[row0 * 64 + (col >> 1)]       = v0;
            H2[(row0 + 8) * 64 + (col >> 1)] = v1;
        }
    }
}

// ---------------- layer-1 gather: build X1 [N_DST1, 256] from g_H1 ---------
__global__ __launch_bounds__(256) void gather1_kernel(const int* __restrict__ nbr1) {
    int warp = (blockIdx.x * blockDim.x + threadIdx.x) >> 5;
    int lane = threadIdx.x & 31;
    if (warp >= N_DST1) return;

    int nj = 0;
    if (lane < FANOUT) nj = nbr1[warp * FANOUT + lane];

    const float4* H = (const float4*)g_H1;                // row stride = 32 float4
    float4 s = H[(size_t)warp * 32 + lane];
    float ax = 0.f, ay = 0.f, az = 0.f, aw = 0.f;
    #pragma unroll
    for (int j = 0; j < FANOUT; j++) {
        int g = __shfl_sync(0xffffffffu, nj, j);
        float4 v = H[(size_t)g * 32 + lane];
        ax += v.x; ay += v.y; az += v.z; aw += v.w;
    }
    const float inv = 1.0f / (float)FANOUT;
    float4* X = (float4*)g_X1;
    X[(size_t)warp * 64 + lane]      = s;
    X[(size_t)warp * 64 + 32 + lane] = make_float4(ax * inv, ay * inv, az * inv, aw * inv);
}

// ---------------- gemm1: out = g_X1 @ g_WfT + g_bf -------------------------
__global__ __launch_bounds__(256) void gemm1_kernel(float* __restrict__ C) {
    __shared__ float Bs[64][65];
    int tid = threadIdx.x;
    int r = blockIdx.x * 4 + (tid >> 6);
    int n = tid & 63;
    float acc = g_bf[n];
    for (int k0 = 0; k0 < 256; k0 += 64) {
        for (int i = tid; i < 64 * 64; i += 256)
            Bs[i >> 6][i & 63] = g_WfT[(size_t)(k0 + (i >> 6)) * 64 + (i & 63)];
        __syncthreads();
        const float* Ar = g_X1 + (size_t)r * 256 + k0;
        #pragma unroll 16
        for (int k = 0; k < 64; k++) acc = fmaf(Ar[k], Bs[k][n], acc);
        __syncthreads();
    }
    C[(size_t)r * 64 + n] = acc;
}

// ---------------- launch ---------------------------------------------------
extern "C" void kernel_launch(void* const* d_in, const int* in_sizes, int n_in,
                              void* d_out, int out_size) {
    const float* emb      = (const float*)d_in[0];
    const float* Ws0      = (const float*)d_in[1];
    const float* bs0      = (const float*)d_in[2];
    const float* Wn0      = (const float*)d_in[3];
    const float* bn0      = (const float*)d_in[4];
    const float* Ws1      = (const float*)d_in[5];
    const float* bs1      = (const float*)d_in[6];
    const float* Wn1      = (const float*)d_in[7];
    const float* bn1      = (const float*)d_in[8];
    const float* Wout     = (const float*)d_in[9];
    const float* bout     = (const float*)d_in[10];
    const int*   in_nodes = (const int*)d_in[11];
    const int*   nbr0     = (const int*)d_in[12];
    const int*   nbr1     = (const int*)d_in[13];
    float* out = (float*)d_out;

    cudaFuncSetAttribute(gather0_cp_kernel,
                         cudaFuncAttributeMaxDynamicSharedMemorySize, GSM_BYTES);

    // weight prep (tiny)
    prep_w0<<<128, 256>>>(Ws0, bs0, Wn0, bn0);
    prep_wf<<<64, 256>>>(Ws1, bs1, Wn1, bn1, Wout, bout);

    // layer 0: cp.async-pipelined gather, then tensor-core GEMM
    gather0_cp_kernel<<<N_DST0 / GCHUNK, 128, GSM_BYTES>>>(emb, in_nodes, nbr0);
    gemm0_tc_kernel<<<N_DST0 / 128, 256>>>();

    // layer 1 gather, then fused (layer1 + output-projection) GEMM
    gather1_kernel<<<(N_DST1 * 32) / 256, 256>>>(nbr1);
    gemm1_kernel<<<N_DST1 / 4, 256>>>(out);
}

// round 8
// speedup vs baseline: 1.3938x; 1.1787x over previous
#include <cuda_runtime.h>
#include <cuda_bf16.h>
#include <cstdint>

// Problem dims
#define NUM_NODES 1000000
#define HIDDEN    128
#define OUT_DIM   64
#define FANOUT    16
#define N_SRC0    1048576
#define N_DST0    65536
#define N_DST1    4096

// ---------------- scratch (static device globals; no allocations) ----------
__device__ uint32_t g_X0[(size_t)N_DST0 * 256];   // tf32 BITS [self|mean]
__device__ float    g_H1[(size_t)N_DST0 * 128];   // layer-0 output (post-ReLU)
__device__ float    g_X1[(size_t)N_DST1 * 256];   // [self | mean] per dst1 row
__device__ uint32_t g_W0T[256 * 128];             // tf32 BITS: [k][n] = cat(Ws0,Wn0)^T
__device__ float    g_b0[128];                    // b_self0 + b_neigh0
__device__ float    g_WfT[256 * 64];              // [k][n] = (W_out @ cat(Ws1,Wn1))^T
__device__ float    g_bf[64];                     // W_out @ (bs1+bn1) + b_out

// ---------------- helpers --------------------------------------------------
__device__ __forceinline__ uint32_t f2tf32(float f) {
    uint32_t r; asm("cvt.rna.tf32.f32 %0, %1;" : "=r"(r) : "f"(f)); return r;
}

__device__ __forceinline__ float4 f4add(float4 a, float4 b) {
    return make_float4(a.x + b.x, a.y + b.y, a.z + b.z, a.w + b.w);
}

__device__ __forceinline__ uint32_t smem_u32(const void* p) {
    uint32_t a;
    asm("{ .reg .u64 t; cvta.to.shared.u64 t, %1; cvt.u32.u64 %0, t; }" : "=r"(a) : "l"(p));
    return a;
}

__device__ __forceinline__ void mma_tf32(float c[4],
                                         uint32_t a0, uint32_t a1, uint32_t a2, uint32_t a3,
                                         uint32_t b0, uint32_t b1) {
    asm volatile(
        "mma.sync.aligned.m16n8k8.row.col.f32.tf32.tf32.f32 "
        "{%0,%1,%2,%3}, {%4,%5,%6,%7}, {%8,%9}, {%0,%1,%2,%3};"
        : "+f"(c[0]), "+f"(c[1]), "+f"(c[2]), "+f"(c[3])
        : "r"(a0), "r"(a1), "r"(a2), "r"(a3), "r"(b0), "r"(b1));
}

// ---------------- prep: pack layer-0 weights (tf32 bits) -------------------
__global__ void prep_w0(const float* __restrict__ Ws0, const float* __restrict__ bs0,
                        const float* __restrict__ Wn0, const float* __restrict__ bn0) {
    int idx = blockIdx.x * blockDim.x + threadIdx.x;   // 32768 total
    if (idx < 256 * 128) {
        int k = idx >> 7;
        int n = idx & 127;
        float v = (k < 128) ? Ws0[n * 128 + k] : Wn0[n * 128 + (k - 128)];
        g_W0T[idx] = f2tf32(v);
    }
    if (idx < 128) g_b0[idx] = bs0[idx] + bn0[idx];
}

// ---------------- prep: fuse layer-1 + output projection -------------------
__global__ void prep_wf(const float* __restrict__ Ws1, const float* __restrict__ bs1,
                        const float* __restrict__ Wn1, const float* __restrict__ bn1,
                        const float* __restrict__ Wout, const float* __restrict__ bout) {
    int idx = blockIdx.x * blockDim.x + threadIdx.x;   // 16384 total
    if (idx < 256 * 64) {
        int k = idx >> 6;
        int n = idx & 63;
        float acc = 0.f;
        if (k < 128) {
            #pragma unroll 4
            for (int r = 0; r < 128; r++) acc += Wout[n * 128 + r] * Ws1[r * 128 + k];
        } else {
            int kk = k - 128;
            #pragma unroll 4
            for (int r = 0; r < 128; r++) acc += Wout[n * 128 + r] * Wn1[r * 128 + kk];
        }
        g_WfT[k * 64 + n] = acc;
    }
    if (idx < 64) {
        float acc = bout[idx];
        #pragma unroll 4
        for (int r = 0; r < 128; r++) acc += Wout[idx * 128 + r] * (bs1[r] + bn1[r]);
        g_bf[idx] = acc;
    }
}

// ---------------- layer-0 gather v2: register-batched loads ----------------
// Warp-per-row; per row the 17 source-row loads issue in two register
// batches (9 + 8 independent __ldg float4) then tree-reduce. 4 CTAs/SM.
__global__ __launch_bounds__(256, 4) void gather0_kernel(
    const float* __restrict__ emb, const int* __restrict__ input_nodes,
    const int* __restrict__ nbr0) {
    __shared__ int s_idx[64 * FANOUT];
    __shared__ int s_self[64];

    const int tid  = threadIdx.x;
    const int lane = tid & 31;
    const int wid  = tid >> 5;
    const int base = blockIdx.x * 64;

    #pragma unroll
    for (int it = 0; it < 4; it++) {
        int i = it * 256 + tid;
        s_idx[i] = input_nodes[nbr0[(size_t)base * FANOUT + i]];
    }
    if (tid < 64) s_self[tid] = input_nodes[base + tid];
    __syncthreads();

    const float4* E = (const float4*)emb;        // row stride = 32 float4
    const float inv = 1.0f / (float)FANOUT;

    #pragma unroll 2
    for (int rr = 0; rr < 8; rr++) {
        const int r = wid * 8 + rr;

        // preload indices into registers
        int gj[FANOUT];
        #pragma unroll
        for (int j = 0; j < FANOUT; j++) gj[j] = s_idx[r * FANOUT + j];
        const int gs = s_self[r];

        // wave 1: self + nbr 0..7 (9 independent loads in flight)
        float4 v0 = __ldg(&E[(size_t)gs * 32 + lane]);
        float4 n0 = __ldg(&E[(size_t)gj[0] * 32 + lane]);
        float4 n1 = __ldg(&E[(size_t)gj[1] * 32 + lane]);
        float4 n2 = __ldg(&E[(size_t)gj[2] * 32 + lane]);
        float4 n3 = __ldg(&E[(size_t)gj[3] * 32 + lane]);
        float4 n4 = __ldg(&E[(size_t)gj[4] * 32 + lane]);
        float4 n5 = __ldg(&E[(size_t)gj[5] * 32 + lane]);
        float4 n6 = __ldg(&E[(size_t)gj[6] * 32 + lane]);
        float4 n7 = __ldg(&E[(size_t)gj[7] * 32 + lane]);
        float4 t0 = f4add(n0, n1), t1 = f4add(n2, n3);
        float4 t2 = f4add(n4, n5), t3 = f4add(n6, n7);
        float4 acc1 = f4add(f4add(t0, t1), f4add(t2, t3));

        // wave 2: nbr 8..15 (8 independent loads in flight)
        float4 m0 = __ldg(&E[(size_t)gj[8]  * 32 + lane]);
        float4 m1 = __ldg(&E[(size_t)gj[9]  * 32 + lane]);
        float4 m2 = __ldg(&E[(size_t)gj[10] * 32 + lane]);
        float4 m3 = __ldg(&E[(size_t)gj[11] * 32 + lane]);
        float4 m4 = __ldg(&E[(size_t)gj[12] * 32 + lane]);
        float4 m5 = __ldg(&E[(size_t)gj[13] * 32 + lane]);
        float4 m6 = __ldg(&E[(size_t)gj[14] * 32 + lane]);
        float4 m7 = __ldg(&E[(size_t)gj[15] * 32 + lane]);
        float4 u0 = f4add(m0, m1), u1 = f4add(m2, m3);
        float4 u2 = f4add(m4, m5), u3 = f4add(m6, m7);
        float4 acc2 = f4add(f4add(u0, u1), f4add(u2, u3));

        float4 acc = f4add(acc1, acc2);

        uint4 ts, tn;
        ts.x = f2tf32(v0.x); ts.y = f2tf32(v0.y); ts.z = f2tf32(v0.z); ts.w = f2tf32(v0.w);
        tn.x = f2tf32(acc.x * inv); tn.y = f2tf32(acc.y * inv);
        tn.z = f2tf32(acc.z * inv); tn.w = f2tf32(acc.w * inv);
        size_t row = (size_t)base + r;
        *(uint4*)&g_X0[row * 256 + lane * 4]       = ts;
        *(uint4*)&g_X0[row * 256 + 128 + lane * 4] = tn;
    }
}

// ---------------- gemm0 (tensor cores, tf32, cp.async double-buffer) -------
// g_H1 = relu(X0 @ W0T + b0).  M=65536, N=128, K=256. 128x128 CTA tile,
// BK=32, 8 warps 2(m) x 4(n), 2-stage cp.async pipeline on A and B.
#define AS_W (128 * 36)
#define BS_W (32 * 132)
#define GEMM0_SM_BYTES ((2 * AS_W + 2 * BS_W) * 4)      // 70656

__global__ __launch_bounds__(256, 2) void gemm0_tc_kernel() {
    extern __shared__ uint32_t sm[];
    uint32_t (*As)[128][36] = (uint32_t (*)[128][36])sm;
    uint32_t (*Bs)[32][132] = (uint32_t (*)[32][132])(sm + 2 * AS_W);

    const int tid  = threadIdx.x;
    const int l    = tid & 31;
    const int lm   = l >> 2;
    const int lk   = l & 3;
    const int wid  = tid >> 5;
    const int wm   = wid >> 2;
    const int wn   = wid & 3;
    const size_t block_row = (size_t)blockIdx.x * 128;
    const uint32_t* __restrict__ A = g_X0 + block_row * 256;
    const uint32_t* __restrict__ B = g_W0T;

    auto prefetch = [&](int chunk) {
        const int s = chunk & 1;
        const int k0 = chunk * 32;
        #pragma unroll
        for (int it = 0; it < 4; it++) {
            int idx = it * 256 + tid;
            int row = idx >> 3;
            int c4  = idx & 7;
            uint32_t d = smem_u32(&As[s][row][c4 * 4]);
            const uint32_t* src = A + (size_t)row * 256 + k0 + c4 * 4;
            asm volatile("cp.async.cg.shared.global [%0], [%1], 16;" :: "r"(d), "l"(src));
        }
        #pragma unroll
        for (int it = 0; it < 4; it++) {
            int idx = it * 256 + tid;
            int kk = idx >> 5;
            int n4 = idx & 31;
            uint32_t d = smem_u32(&Bs[s][kk][n4 * 4]);
            const uint32_t* src = B + (size_t)(k0 + kk) * 128 + n4 * 4;
            asm volatile("cp.async.cg.shared.global [%0], [%1], 16;" :: "r"(d), "l"(src));
        }
        asm volatile("cp.async.commit_group;" ::: "memory");
    };

    float acc[4][4][4];
    #pragma unroll
    for (int i = 0; i < 4; i++)
        #pragma unroll
        for (int j = 0; j < 4; j++)
            #pragma unroll
            for (int c = 0; c < 4; c++) acc[i][j][c] = 0.f;

    prefetch(0);
    prefetch(1);

    #pragma unroll
    for (int ch = 0; ch < 8; ch++) {
        const int s = ch & 1;
        if (ch < 7) {
            asm volatile("cp.async.wait_group 1;" ::: "memory");
        } else {
            asm volatile("cp.async.wait_group 0;" ::: "memory");
        }
        __syncthreads();

        #pragma unroll
        for (int kk = 0; kk < 4; kk++) {
            const int k8 = kk * 8;
            uint32_t af[4][4], bf[4][2];
            #pragma unroll
            for (int mt = 0; mt < 4; mt++) {
                int mrow = wm * 64 + mt * 16 + lm;
                af[mt][0] = As[s][mrow    ][k8 + lk];
                af[mt][1] = As[s][mrow + 8][k8 + lk];
                af[mt][2] = As[s][mrow    ][k8 + lk + 4];
                af[mt][3] = As[s][mrow + 8][k8 + lk + 4];
            }
            #pragma unroll
            for (int nt = 0; nt < 4; nt++) {
                int ncol = wn * 32 + nt * 8 + lm;
                bf[nt][0] = Bs[s][k8 + lk    ][ncol];
                bf[nt][1] = Bs[s][k8 + lk + 4][ncol];
            }
            #pragma unroll
            for (int mt = 0; mt < 4; mt++)
                #pragma unroll
                for (int nt = 0; nt < 4; nt++)
                    mma_tf32(acc[mt][nt], af[mt][0], af[mt][1], af[mt][2], af[mt][3],
                             bf[nt][0], bf[nt][1]);
        }
        __syncthreads();
        if (ch + 2 < 8) prefetch(ch + 2);
    }

    float2* __restrict__ H2 = (float2*)g_H1;      // row stride = 64 float2
    #pragma unroll
    for (int nt = 0; nt < 4; nt++) {
        int col = wn * 32 + nt * 8 + lk * 2;
        float bv0 = g_b0[col], bv1 = g_b0[col + 1];
        #pragma unroll
        for (int mt = 0; mt < 4; mt++) {
            size_t row0 = block_row + wm * 64 + mt * 16 + lm;
            float2 v0 = make_float2(fmaxf(acc[mt][nt][0] + bv0, 0.f),
                                    fmaxf(acc[mt][nt][1] + bv1, 0.f));
            float2 v1 = make_float2(fmaxf(acc[mt][nt][2] + bv0, 0.f),
                                    fmaxf(acc[mt][nt][3] + bv1, 0.f));
            H2[row0 * 64 + (col >> 1)]       = v0;
            H2[(row0 + 8) * 64 + (col >> 1)] = v1;
        }
    }
}

// ---------------- layer-1 gather: build X1 [N_DST1, 256] from g_H1 ---------
__global__ __launch_bounds__(256) void gather1_kernel(const int* __restrict__ nbr1) {
    int warp = (blockIdx.x * blockDim.x + threadIdx.x) >> 5;
    int lane = threadIdx.x & 31;
    if (warp >= N_DST1) return;

    int nj = 0;
    if (lane < FANOUT) nj = nbr1[warp * FANOUT + lane];

    const float4* H = (const float4*)g_H1;                // row stride = 32 float4
    float4 s = H[(size_t)warp * 32 + lane];
    float ax = 0.f, ay = 0.f, az = 0.f, aw = 0.f;
    #pragma unroll
    for (int j = 0; j < FANOUT; j++) {
        int g = __shfl_sync(0xffffffffu, nj, j);
        float4 v = H[(size_t)g * 32 + lane];
        ax += v.x; ay += v.y; az += v.z; aw += v.w;
    }
    const float inv = 1.0f / (float)FANOUT;
    float4* X = (float4*)g_X1;
    X[(size_t)warp * 64 + lane]      = s;
    X[(size_t)warp * 64 + 32 + lane] = make_float4(ax * inv, ay * inv, az * inv, aw * inv);
}

// ---------------- gemm1: out = g_X1 @ g_WfT + g_bf -------------------------
__global__ __launch_bounds__(256) void gemm1_kernel(float* __restrict__ C) {
    __shared__ float Bs[64][65];
    int tid = threadIdx.x;
    int r = blockIdx.x * 4 + (tid >> 6);
    int n = tid & 63;
    float acc = g_bf[n];
    for (int k0 = 0; k0 < 256; k0 += 64) {
        for (int i = tid; i < 64 * 64; i += 256)
            Bs[i >> 6][i & 63] = g_WfT[(size_t)(k0 + (i >> 6)) * 64 + (i & 63)];
        __syncthreads();
        const float* Ar = g_X1 + (size_t)r * 256 + k0;
        #pragma unroll 16
        for (int k = 0; k < 64; k++) acc = fmaf(Ar[k], Bs[k][n], acc);
        __syncthreads();
    }
    C[(size_t)r * 64 + n] = acc;
}

// ---------------- launch ---------------------------------------------------
extern "C" void kernel_launch(void* const* d_in, const int* in_sizes, int n_in,
                              void* d_out, int out_size) {
    const float* emb      = (const float*)d_in[0];
    const float* Ws0      = (const float*)d_in[1];
    const float* bs0      = (const float*)d_in[2];
    const float* Wn0      = (const float*)d_in[3];
    const float* bn0      = (const float*)d_in[4];
    const float* Ws1      = (const float*)d_in[5];
    const float* bs1      = (const float*)d_in[6];
    const float* Wn1      = (const float*)d_in[7];
    const float* bn1      = (const float*)d_in[8];
    const float* Wout     = (const float*)d_in[9];
    const float* bout     = (const float*)d_in[10];
    const int*   in_nodes = (const int*)d_in[11];
    const int*   nbr0     = (const int*)d_in[12];
    const int*   nbr1     = (const int*)d_in[13];
    float* out = (float*)d_out;

    cudaFuncSetAttribute(gemm0_tc_kernel,
                         cudaFuncAttributeMaxDynamicSharedMemorySize, GEMM0_SM_BYTES);

    // weight prep (tiny)
    prep_w0<<<128, 256>>>(Ws0, bs0, Wn0, bn0);
    prep_wf<<<64, 256>>>(Ws1, bs1, Wn1, bn1, Wout, bout);

    // layer 0: MLP-batched gather, then double-buffered tensor-core GEMM
    gather0_kernel<<<N_DST0 / 64, 256>>>(emb, in_nodes, nbr0);
    gemm0_tc_kernel<<<N_DST0 / 128, 256, GEMM0_SM_BYTES>>>();

    // layer 1 gather, then fused (layer1 + output-projection) GEMM
    gather1_kernel<<<(N_DST1 * 32) / 256, 256>>>(nbr1);
    gemm1_kernel<<<N_DST1 / 4, 256>>>(out);
}

// round 9
// speedup vs baseline: 1.4128x; 1.0137x over previous
#include <cuda_runtime.h>
#include <cuda_bf16.h>
#include <cstdint>

// Problem dims
#define NUM_NODES 1000000
#define HIDDEN    128
#define OUT_DIM   64
#define FANOUT    16
#define N_SRC0    1048576
#define N_DST0    65536
#define N_DST1    4096

// ---------------- scratch (static device globals; no allocations) ----------
__device__ uint32_t g_X0[(size_t)N_DST0 * 256];   // tf32 BITS [self|mean]
__device__ float    g_H1[(size_t)N_DST0 * 128];   // layer-0 output (post-ReLU)
__device__ uint32_t g_W0T[256 * 128];             // tf32 BITS: [k][n] = cat(Ws0,Wn0)^T
__device__ float    g_b0[128];                    // b_self0 + b_neigh0
__device__ float    g_WfT[256 * 64];              // [k][n] = (W_out @ cat(Ws1,Wn1))^T
__device__ float    g_bf[64];                     // W_out @ (bs1+bn1) + b_out

// ---------------- helpers --------------------------------------------------
__device__ __forceinline__ uint32_t f2tf32(float f) {
    uint32_t r; asm("cvt.rna.tf32.f32 %0, %1;" : "=r"(r) : "f"(f)); return r;
}

__device__ __forceinline__ float4 f4add(float4 a, float4 b) {
    return make_float4(a.x + b.x, a.y + b.y, a.z + b.z, a.w + b.w);
}

__device__ __forceinline__ uint32_t smem_u32(const void* p) {
    uint32_t a;
    asm("{ .reg .u64 t; cvta.to.shared.u64 t, %1; cvt.u32.u64 %0, t; }" : "=r"(a) : "l"(p));
    return a;
}

__device__ __forceinline__ void mma_tf32(float c[4],
                                         uint32_t a0, uint32_t a1, uint32_t a2, uint32_t a3,
                                         uint32_t b0, uint32_t b1) {
    asm volatile(
        "mma.sync.aligned.m16n8k8.row.col.f32.tf32.tf32.f32 "
        "{%0,%1,%2,%3}, {%4,%5,%6,%7}, {%8,%9}, {%0,%1,%2,%3};"
        : "+f"(c[0]), "+f"(c[1]), "+f"(c[2]), "+f"(c[3])
        : "r"(a0), "r"(a1), "r"(a2), "r"(a3), "r"(b0), "r"(b1));
}

// ---------------- prep (merged): W0 pack + layer1/out fusion ---------------
__global__ void prep_all(const float* __restrict__ Ws0, const float* __restrict__ bs0,
                         const float* __restrict__ Wn0, const float* __restrict__ bn0,
                         const float* __restrict__ Ws1, const float* __restrict__ bs1,
                         const float* __restrict__ Wn1, const float* __restrict__ bn1,
                         const float* __restrict__ Wout, const float* __restrict__ bout) {
    if (blockIdx.x < 128) {
        int idx = blockIdx.x * 256 + threadIdx.x;       // 0..32767
        int k = idx >> 7;
        int n = idx & 127;
        float v = (k < 128) ? Ws0[n * 128 + k] : Wn0[n * 128 + (k - 128)];
        g_W0T[idx] = f2tf32(v);
        if (idx < 128) g_b0[idx] = bs0[idx] + bn0[idx];
    } else {
        int idx = (blockIdx.x - 128) * 256 + threadIdx.x;   // 0..16383
        int k = idx >> 6;
        int n = idx & 63;
        float acc = 0.f;
        if (k < 128) {
            #pragma unroll 4
            for (int r = 0; r < 128; r++) acc += Wout[n * 128 + r] * Ws1[r * 128 + k];
        } else {
            int kk = k - 128;
            #pragma unroll 4
            for (int r = 0; r < 128; r++) acc += Wout[n * 128 + r] * Wn1[r * 128 + kk];
        }
        g_WfT[k * 64 + n] = acc;
        if (idx < 64) {
            float a2 = bout[idx];
            #pragma unroll 4
            for (int r = 0; r < 128; r++) a2 += Wout[idx * 128 + r] * (bs1[r] + bn1[r]);
            g_bf[idx] = a2;
        }
    }
}

// ---------------- layer-0 gather: register-batched loads (R8, proven) ------
__global__ __launch_bounds__(256, 4) void gather0_kernel(
    const float* __restrict__ emb, const int* __restrict__ input_nodes,
    const int* __restrict__ nbr0) {
    __shared__ int s_idx[64 * FANOUT];
    __shared__ int s_self[64];

    const int tid  = threadIdx.x;
    const int lane = tid & 31;
    const int wid  = tid >> 5;
    const int base = blockIdx.x * 64;

    #pragma unroll
    for (int it = 0; it < 4; it++) {
        int i = it * 256 + tid;
        s_idx[i] = input_nodes[nbr0[(size_t)base * FANOUT + i]];
    }
    if (tid < 64) s_self[tid] = input_nodes[base + tid];
    __syncthreads();

    const float4* E = (const float4*)emb;        // row stride = 32 float4
    const float inv = 1.0f / (float)FANOUT;

    #pragma unroll 2
    for (int rr = 0; rr < 8; rr++) {
        const int r = wid * 8 + rr;

        int gj[FANOUT];
        #pragma unroll
        for (int j = 0; j < FANOUT; j++) gj[j] = s_idx[r * FANOUT + j];
        const int gs = s_self[r];

        float4 v0 = __ldg(&E[(size_t)gs * 32 + lane]);
        float4 n0 = __ldg(&E[(size_t)gj[0] * 32 + lane]);
        float4 n1 = __ldg(&E[(size_t)gj[1] * 32 + lane]);
        float4 n2 = __ldg(&E[(size_t)gj[2] * 32 + lane]);
        float4 n3 = __ldg(&E[(size_t)gj[3] * 32 + lane]);
        float4 n4 = __ldg(&E[(size_t)gj[4] * 32 + lane]);
        float4 n5 = __ldg(&E[(size_t)gj[5] * 32 + lane]);
        float4 n6 = __ldg(&E[(size_t)gj[6] * 32 + lane]);
        float4 n7 = __ldg(&E[(size_t)gj[7] * 32 + lane]);
        float4 t0 = f4add(n0, n1), t1 = f4add(n2, n3);
        float4 t2 = f4add(n4, n5), t3 = f4add(n6, n7);
        float4 acc1 = f4add(f4add(t0, t1), f4add(t2, t3));

        float4 m0 = __ldg(&E[(size_t)gj[8]  * 32 + lane]);
        float4 m1 = __ldg(&E[(size_t)gj[9]  * 32 + lane]);
        float4 m2 = __ldg(&E[(size_t)gj[10] * 32 + lane]);
        float4 m3 = __ldg(&E[(size_t)gj[11] * 32 + lane]);
        float4 m4 = __ldg(&E[(size_t)gj[12] * 32 + lane]);
        float4 m5 = __ldg(&E[(size_t)gj[13] * 32 + lane]);
        float4 m6 = __ldg(&E[(size_t)gj[14] * 32 + lane]);
        float4 m7 = __ldg(&E[(size_t)gj[15] * 32 + lane]);
        float4 u0 = f4add(m0, m1), u1 = f4add(m2, m3);
        float4 u2 = f4add(m4, m5), u3 = f4add(m6, m7);
        float4 acc2 = f4add(f4add(u0, u1), f4add(u2, u3));

        float4 acc = f4add(acc1, acc2);

        uint4 ts, tn;
        ts.x = f2tf32(v0.x); ts.y = f2tf32(v0.y); ts.z = f2tf32(v0.z); ts.w = f2tf32(v0.w);
        tn.x = f2tf32(acc.x * inv); tn.y = f2tf32(acc.y * inv);
        tn.z = f2tf32(acc.z * inv); tn.w = f2tf32(acc.w * inv);
        size_t row = (size_t)base + r;
        *(uint4*)&g_X0[row * 256 + lane * 4]       = ts;
        *(uint4*)&g_X0[row * 256 + 128 + lane * 4] = tn;
    }
}

// ---------------- gemm0: tf32 MMA, 3-stage cp.async, 1 sync/iter -----------
// g_H1 = relu(X0 @ W0T + b0).  M=65536, N=128, K=256. 128x128 CTA tile,
// BK=32, 8 warps 2(m) x 4(n).
#define AS_W (128 * 36)
#define BS_W (32 * 132)
#define STG_W (AS_W + BS_W)                       // 8832 words per stage
#define GEMM0_SM_BYTES (3 * STG_W * 4)            // 105984

__global__ __launch_bounds__(256, 2) void gemm0_tc_kernel() {
    extern __shared__ uint32_t sm[];

    const int tid  = threadIdx.x;
    const int l    = tid & 31;
    const int lm   = l >> 2;
    const int lk   = l & 3;
    const int wid  = tid >> 5;
    const int wm   = wid >> 2;
    const int wn   = wid & 3;
    const size_t block_row = (size_t)blockIdx.x * 128;
    const uint32_t* __restrict__ A = g_X0 + block_row * 256;
    const uint32_t* __restrict__ B = g_W0T;

    auto stageA = [&](int s) -> uint32_t (*)[36] {
        return (uint32_t (*)[36])(sm + s * STG_W);
    };
    auto stageB = [&](int s) -> uint32_t (*)[132] {
        return (uint32_t (*)[132])(sm + s * STG_W + AS_W);
    };

    auto prefetch = [&](int chunk) {
        const int s = chunk % 3;
        const int k0 = chunk * 32;
        uint32_t (*As)[36] = stageA(s);
        uint32_t (*Bs)[132] = stageB(s);
        #pragma unroll
        for (int it = 0; it < 4; it++) {
            int idx = it * 256 + tid;
            int row = idx >> 3;
            int c4  = idx & 7;
            uint32_t d = smem_u32(&As[row][c4 * 4]);
            const uint32_t* src = A + (size_t)row * 256 + k0 + c4 * 4;
            asm volatile("cp.async.cg.shared.global [%0], [%1], 16;" :: "r"(d), "l"(src));
        }
        #pragma unroll
        for (int it = 0; it < 4; it++) {
            int idx = it * 256 + tid;
            int kk = idx >> 5;
            int n4 = idx & 31;
            uint32_t d = smem_u32(&Bs[kk][n4 * 4]);
            const uint32_t* src = B + (size_t)(k0 + kk) * 128 + n4 * 4;
            asm volatile("cp.async.cg.shared.global [%0], [%1], 16;" :: "r"(d), "l"(src));
        }
        asm volatile("cp.async.commit_group;" ::: "memory");
    };

    float acc[4][4][4];
    #pragma unroll
    for (int i = 0; i < 4; i++)
        #pragma unroll
        for (int j = 0; j < 4; j++)
            #pragma unroll
            for (int c = 0; c < 4; c++) acc[i][j][c] = 0.f;

    prefetch(0);
    prefetch(1);

    #pragma unroll
    for (int ch = 0; ch < 8; ch++) {
        const int s = ch % 3;
        // group ch complete when pending <= issued_max - ch (== 1 except last)
        if (ch < 7) {
            asm volatile("cp.async.wait_group 1;" ::: "memory");
        } else {
            asm volatile("cp.async.wait_group 0;" ::: "memory");
        }
        __syncthreads();
        if (ch + 2 < 8) prefetch(ch + 2);   // writes buffer (ch+2)%3 — free

        uint32_t (*As)[36] = stageA(s);
        uint32_t (*Bs)[132] = stageB(s);
        #pragma unroll
        for (int kk = 0; kk < 4; kk++) {
            const int k8 = kk * 8;
            uint32_t af[4][4], bf[4][2];
            #pragma unroll
            for (int mt = 0; mt < 4; mt++) {
                int mrow = wm * 64 + mt * 16 + lm;
                af[mt][0] = As[mrow    ][k8 + lk];
                af[mt][1] = As[mrow + 8][k8 + lk];
                af[mt][2] = As[mrow    ][k8 + lk + 4];
                af[mt][3] = As[mrow + 8][k8 + lk + 4];
            }
            #pragma unroll
            for (int nt = 0; nt < 4; nt++) {
                int ncol = wn * 32 + nt * 8 + lm;
                bf[nt][0] = Bs[k8 + lk    ][ncol];
                bf[nt][1] = Bs[k8 + lk + 4][ncol];
            }
            #pragma unroll
            for (int mt = 0; mt < 4; mt++)
                #pragma unroll
                for (int nt = 0; nt < 4; nt++)
                    mma_tf32(acc[mt][nt], af[mt][0], af[mt][1], af[mt][2], af[mt][3],
                             bf[nt][0], bf[nt][1]);
        }
    }

    float2* __restrict__ H2 = (float2*)g_H1;      // row stride = 64 float2
    #pragma unroll
    for (int nt = 0; nt < 4; nt++) {
        int col = wn * 32 + nt * 8 + lk * 2;
        float bv0 = g_b0[col], bv1 = g_b0[col + 1];
        #pragma unroll
        for (int mt = 0; mt < 4; mt++) {
            size_t row0 = block_row + wm * 64 + mt * 16 + lm;
            float2 v0 = make_float2(fmaxf(acc[mt][nt][0] + bv0, 0.f),
                                    fmaxf(acc[mt][nt][1] + bv1, 0.f));
            float2 v1 = make_float2(fmaxf(acc[mt][nt][2] + bv0, 0.f),
                                    fmaxf(acc[mt][nt][3] + bv1, 0.f));
            H2[row0 * 64 + (col >> 1)]       = v0;
            H2[(row0 + 8) * 64 + (col >> 1)] = v1;
        }
    }
}

// ---------------- layer-1 fused: gather + mean + GEMM + bias ---------------
// Per block: 32 dst1 rows. Phase 1: 8 warps gather [self|mean] into smem X
// tile. Phase 2: SIMT GEMM 32x64 (K=256) with Wf chunks from L2.
__global__ __launch_bounds__(256) void layer1_kernel(
    const int* __restrict__ nbr1, float* __restrict__ C) {
    __shared__ float Xs[32][260];
    __shared__ float Bs[64][72];

    const int tid  = threadIdx.x;
    const int lane = tid & 31;
    const int wid  = tid >> 5;
    const int base = blockIdx.x * 32;

    // phase 1: gather 4 rows per warp
    const float4* H = (const float4*)g_H1;          // row stride = 32 float4
    const float inv = 1.0f / (float)FANOUT;
    #pragma unroll
    for (int rr = 0; rr < 4; rr++) {
        const int r = wid * 4 + rr;
        int nj = (lane < FANOUT) ? nbr1[(size_t)(base + r) * FANOUT + lane] : 0;
        float4 s = __ldg(&H[(size_t)(base + r) * 32 + lane]);
        float ax = 0.f, ay = 0.f, az = 0.f, aw = 0.f;
        #pragma unroll
        for (int j = 0; j < FANOUT; j++) {
            int g = __shfl_sync(0xffffffffu, nj, j);
            float4 v = __ldg(&H[(size_t)g * 32 + lane]);
            ax += v.x; ay += v.y; az += v.z; aw += v.w;
        }
        *(float4*)&Xs[r][lane * 4] = s;
        *(float4*)&Xs[r][128 + lane * 4] =
            make_float4(ax * inv, ay * inv, az * inv, aw * inv);
    }
    __syncthreads();

    // phase 2: out[base+r][n] = sum_k Xs[r][k] * WfT[k][n] + bf[n]
    const int r  = tid >> 3;            // 0..31
    const int nb = (tid & 7) * 8;       // 0..56
    float acc[8];
    #pragma unroll
    for (int j = 0; j < 8; j++) acc[j] = g_bf[nb + j];

    for (int k0 = 0; k0 < 256; k0 += 64) {
        #pragma unroll
        for (int it = 0; it < 16; it++) {
            int i = it * 256 + tid;
            Bs[i >> 6][i & 63] = g_WfT[(size_t)(k0 + (i >> 6)) * 64 + (i & 63)];
        }
        __syncthreads();
        #pragma unroll 8
        for (int k = 0; k < 64; k++) {
            float xv = Xs[r][k0 + k];
            float4 b0 = *(float4*)&Bs[k][nb];
            float4 b1 = *(float4*)&Bs[k][nb + 4];
            acc[0] = fmaf(xv, b0.x, acc[0]);
            acc[1] = fmaf(xv, b0.y, acc[1]);
            acc[2] = fmaf(xv, b0.z, acc[2]);
            acc[3] = fmaf(xv, b0.w, acc[3]);
            acc[4] = fmaf(xv, b1.x, acc[4]);
            acc[5] = fmaf(xv, b1.y, acc[5]);
            acc[6] = fmaf(xv, b1.z, acc[6]);
            acc[7] = fmaf(xv, b1.w, acc[7]);
        }
        __syncthreads();
    }

    float4* Co = (float4*)(C + (size_t)(base + r) * 64 + nb);
    Co[0] = make_float4(acc[0], acc[1], acc[2], acc[3]);
    Co[1] = make_float4(acc[4], acc[5], acc[6], acc[7]);
}

// ---------------- launch ---------------------------------------------------
extern "C" void kernel_launch(void* const* d_in, const int* in_sizes, int n_in,
                              void* d_out, int out_size) {
    const float* emb      = (const float*)d_in[0];
    const float* Ws0      = (const float*)d_in[1];
    const float* bs0      = (const float*)d_in[2];
    const float* Wn0      = (const float*)d_in[3];
    const float* bn0      = (const float*)d_in[4];
    const float* Ws1      = (const float*)d_in[5];
    const float* bs1      = (const float*)d_in[6];
    const float* Wn1      = (const float*)d_in[7];
    const float* bn1      = (const float*)d_in[8];
    const float* Wout     = (const float*)d_in[9];
    const float* bout     = (const float*)d_in[10];
    const int*   in_nodes = (const int*)d_in[11];
    const int*   nbr0     = (const int*)d_in[12];
    const int*   nbr1     = (const int*)d_in[13];
    float* out = (float*)d_out;

    cudaFuncSetAttribute(gemm0_tc_kernel,
                         cudaFuncAttributeMaxDynamicSharedMemorySize, GEMM0_SM_BYTES);

    // merged weight prep
    prep_all<<<192, 256>>>(Ws0, bs0, Wn0, bn0, Ws1, bs1, Wn1, bn1, Wout, bout);

    // layer 0: MLP-batched gather, then 3-stage tensor-core GEMM
    gather0_kernel<<<N_DST0 / 64, 256>>>(emb, in_nodes, nbr0);
    gemm0_tc_kernel<<<N_DST0 / 128, 256, GEMM0_SM_BYTES>>>();

    // layer 1 + output projection, fully fused
    layer1_kernel<<<N_DST1 / 32, 256>>>(nbr1, out);
}